// round 14
// baseline (speedup 1.0000x reference)
#include <cuda_runtime.h>
#include <cstdint>

#define EN 2048
#define IN_ 256
#define TN 256
#define BN 32
#define EWORDS 64
#define IWORDS 8
#define NT 512      // threads per CTA; thread t owns exc neurons t, t+512, t+1024, t+1536

// c-order: c(j) = 4*(j&511) + (j>>9)  <->  j(c) = (c>>2) + 512*(c&3)
// thread t's 4 neurons occupy c = 4t..4t+3  -> float4/uint4 loads.

__device__ __align__(16) uint32_t g_wrecP[EWORDS * EN];  // [w][c] packed w_rec bits (512KB)
__device__ __align__(16) float    g_wieP[IN_ * EN];      // [i][c] = w_ie[i][j(c)]  (2MB)
__device__ __align__(16) float    g_rowsumP[EN];         // [c] popcount of w_rec row j(c)
__device__ __align__(16) float    g_cs_wieP[EN];         // [c] sum_i w_ie[i][j(c)] (ascending i)
__device__ float    g_cs_wei[IN_];                       // [i] sum_e w_ei[e][i] (ascending e)
__device__ int      g_rsmin;
__device__ uint32_t g_cwie_max_u, g_xmax_u;

// ---------------- prep 1: pack/permute weights + reset markers ----------------
__global__ void prep1(const float* __restrict__ wrec,
                      const float* __restrict__ wie) {
    const int bid = blockIdx.x, tid = threadIdx.x;
    if (bid == 0 && tid == 0) {
        g_rsmin = 0x7fffffff;
        g_cwie_max_u = 0u;
        g_xmax_u = 0u;
    }
    if (bid < 512) {
        // A: pack w_rec -> wrecP.  idx = j*64 + w
        int idx = bid * 256 + tid;
        int j = idx >> 6, w = idx & 63;
        const uint4* p = reinterpret_cast<const uint4*>(wrec + (size_t)j * EN + (size_t)w * 32);
        uint32_t m = 0;
#pragma unroll
        for (int k = 0; k < 8; k++) {
            uint4 f = p[k];   // entries exactly 0.0f or 1.0f
            m |= (f.x ? 1u : 0u) << (k * 4 + 0);
            m |= (f.y ? 1u : 0u) << (k * 4 + 1);
            m |= (f.z ? 1u : 0u) << (k * 4 + 2);
            m |= (f.w ? 1u : 0u) << (k * 4 + 3);
        }
        int c = 4 * (j & 511) + (j >> 9);
        g_wrecP[w * EN + c] = m;
    } else {
        // B: permute w_ie -> wieP. u enumerates (i, j-group of 4)
        int u = (bid - 512) * 256 + tid;         // 0..131071
        int i = u >> 9, jq = u & 511;
        float4 f = reinterpret_cast<const float4*>(wie + (size_t)i * EN)[jq];
        int j0 = 4 * jq;
        float vals[4] = {f.x, f.y, f.z, f.w};
#pragma unroll
        for (int q = 0; q < 4; q++) {
            int j = j0 + q;
            int c = 4 * (j & 511) + (j >> 9);
            g_wieP[(size_t)i * EN + c] = vals[q];
        }
    }
}

// ---------------- prep 2: sums + invariant bounds + max|x| ----------------
__global__ void prep2(const float* __restrict__ x, const float* __restrict__ wei) {
    const int bid = blockIdx.x, tid = threadIdx.x, lane = tid & 31;
    if (bid < 8) {
        int c = bid * 256 + tid;  // c-order index 0..2047
        int cnt = 0;
#pragma unroll 8
        for (int w = 0; w < EWORDS; w++) cnt += __popc(g_wrecP[w * EN + c]);
        g_rowsumP[c] = (float)cnt;
        atomicMin(&g_rsmin, cnt);
        float s = 0.f;
#pragma unroll 4
        for (int i = 0; i < IN_; i++) s = __fadd_rn(s, g_wieP[(size_t)i * EN + c]);
        g_cs_wieP[c] = s;
        atomicMax(&g_cwie_max_u, __float_as_uint(s));  // s >= 0: bits monotone
    } else if (bid == 8) {
        // cs_wei[i] = sum_e wei[e][i], ascending e, exact chain; coalesced across i
        if (tid < IN_) {
            float q = 0.f;
#pragma unroll 4
            for (int e = 0; e < EN; e++)
                q = __fadd_rn(q, wei[(size_t)e * IN_ + tid]);
            g_cs_wei[tid] = q;
        }
    } else {
        const float4* x4 = reinterpret_cast<const float4*>(x);
        const int n4 = (TN * BN * EN) / 4;
        int i = (bid - 9) * 256 + tid;
        const int stride = 256 * 256;
        float m = 0.f;
        for (; i < n4; i += stride) {
            float4 f = x4[i];
            m = fmaxf(m, fmaxf(fmaxf(fabsf(f.x), fabsf(f.y)), fmaxf(fabsf(f.z), fabsf(f.w))));
        }
#pragma unroll
        for (int off = 16; off > 0; off >>= 1)
            m = fmaxf(m, __shfl_xor_sync(0xffffffffu, m, off));
        if (lane == 0) atomicMax(&g_xmax_u, __float_as_uint(m));
    }
}

// ---------------- main simulator: one CTA per batch, coalesced select-dense gathers ----------------
__global__ __launch_bounds__(NT, 1)
void sim_kernel(const float* __restrict__ x,
                const float* __restrict__ wei,
                float* __restrict__ out)
{
    __shared__ uint32_t s_ez[2][EWORDS];
    __shared__ uint32_t s_iz[2][IWORDS];
    __shared__ __align__(16) unsigned char s_fb[2][16];
    __shared__ __align__(16) unsigned char s_cnt[2][16];

    const int t    = threadIdx.x;
    const int b    = blockIdx.x;
    const int warp = t >> 5, lane = t & 31;

    float v0 = 0.f, v1 = 0.f, v2 = 0.f, v3 = 0.f;
    float c0 = 0.f, c1 = 0.f, c2 = 0.f, c3 = 0.f;
    float iv = 0.f, ii = 0.f;                      // inh neuron t (t < 256)

    const float cwei = (t < IN_) ? g_cs_wei[t] : 0.f;

    // absorbing-saturation invariant (exc-only, proven sufficient; see R8):
    const int g_ok =
        __fadd_rn((float)g_rsmin,
                  -__fadd_rn(__uint_as_float(g_cwie_max_u), __uint_as_float(g_xmax_u))) >= 13.0f;

    const uint4*  wrecP4 = reinterpret_cast<const uint4*>(g_wrecP);    // [w*512 + t]
    const float4* wieP4  = reinterpret_cast<const float4*>(g_wieP);    // [i*512 + t]
    const float4* rsP4   = reinterpret_cast<const float4*>(g_rowsumP);
    const float4* cwP4   = reinterpret_cast<const float4*>(g_cs_wieP);

    if (t < EWORDS) s_ez[1][t] = 0u;
    if (t < IWORDS) s_iz[1][t] = 0u;
    __syncthreads();

    int pe_all = 0, pe_any = 0, pi_all = 0, pi_any = 0;
    int ts = TN;

    // depth-2 x pipeline: xc = x[st], xn = x[st+1]
    float xc0 = x[(size_t)b * EN + t];
    float xc1 = x[(size_t)b * EN + t + 512];
    float xc2 = x[(size_t)b * EN + t + 1024];
    float xc3 = x[(size_t)b * EN + t + 1536];
    float xn0 = x[((size_t)1 * BN + b) * EN + t];
    float xn1 = x[((size_t)1 * BN + b) * EN + t + 512];
    float xn2 = x[((size_t)1 * BN + b) * EN + t + 1024];
    float xn3 = x[((size_t)1 * BN + b) * EN + t + 1536];

    for (int st = 0; st < TN; st++) {
        const int wp = st & 1, rp = wp ^ 1;

        // ---- [a] recurrent term (integer-exact popcount) ----
        float rec0, rec1, rec2, rec3;
        if (pe_all) {
            float4 r = rsP4[t];
            rec0 = r.x; rec1 = r.y; rec2 = r.z; rec3 = r.w;
        } else if (!pe_any) {
            rec0 = rec1 = rec2 = rec3 = 0.f;
        } else {
            int a0 = 0, a1 = 0, a2 = 0, a3 = 0;
#pragma unroll 8
            for (int w = 0; w < EWORDS; w++) {
                uint32_t m = s_ez[rp][w];
                uint4 q = wrecP4[w * 512 + t];
                a0 += __popc(m & q.x); a1 += __popc(m & q.y);
                a2 += __popc(m & q.z); a3 += __popc(m & q.w);
            }
            rec0 = (float)a0; rec1 = (float)a1; rec2 = (float)a2; rec3 = (float)a3;
        }

        // ---- [a] inhibitory feedback: scan <=24, select-dense otherwise (R12 proven) ----
        float inh0, inh1, inh2, inh3;
        if (pi_all) {
            float4 cwv = cwP4[t];
            inh0 = cwv.x; inh1 = cwv.y; inh2 = cwv.z; inh3 = cwv.w;
        } else if (!pi_any) {
            inh0 = inh1 = inh2 = inh3 = 0.f;
        } else {
            uint4 ma = *reinterpret_cast<const uint4*>(&s_iz[rp][0]);
            uint4 mb = *reinterpret_cast<const uint4*>(&s_iz[rp][4]);
            uint32_t mw[IWORDS] = {ma.x, ma.y, ma.z, ma.w, mb.x, mb.y, mb.z, mb.w};
            int icnt = __popc(ma.x) + __popc(ma.y) + __popc(ma.z) + __popc(ma.w)
                     + __popc(mb.x) + __popc(mb.y) + __popc(mb.z) + __popc(mb.w);
            inh0 = inh1 = inh2 = inh3 = 0.f;
            if (icnt <= 24) {
                // few spikes: exact ascending-i scan (bounded iterations)
                for (int w = 0; w < IWORDS; w++) {
                    uint32_t m = mw[w];
                    while (m) {
                        int r = __ffs(m) - 1; m &= m - 1;
                        float4 wv = wieP4[(w * 32 + r) * 512 + t];
                        inh0 = __fadd_rn(inh0, wv.x); inh1 = __fadd_rn(inh1, wv.y);
                        inh2 = __fadd_rn(inh2, wv.z); inh3 = __fadd_rn(inh3, wv.w);
                    }
                }
            } else {
                // select-dense: unconditional coalesced float4 loads; fadd(s,+0.0) == s exactly
                for (int w = 0; w < IWORDS; w++) {
                    uint32_t m = mw[w];
#pragma unroll 8
                    for (int r = 0; r < 32; r++) {
                        float4 wv = wieP4[(w * 32 + r) * 512 + t];
                        bool on = (m >> r) & 1u;
                        inh0 = __fadd_rn(inh0, on ? wv.x : 0.0f);
                        inh1 = __fadd_rn(inh1, on ? wv.y : 0.0f);
                        inh2 = __fadd_rn(inh2, on ? wv.z : 0.0f);
                        inh3 = __fadd_rn(inh3, on ? wv.w : 0.0f);
                    }
                }
            }
        }

        // ---- [b] excitatory update (JAX-exact rounding order) ----
        float id0 = __fadd_rn(c0, __fmul_rn(-0.2f, c0));
        float vd0 = __fadd_rn(v0, __fmul_rn(0.1f, __fadd_rn(__fsub_rn(0.f, v0), c0)));
        float id1 = __fadd_rn(c1, __fmul_rn(-0.2f, c1));
        float vd1 = __fadd_rn(v1, __fmul_rn(0.1f, __fadd_rn(__fsub_rn(0.f, v1), c1)));
        float id2 = __fadd_rn(c2, __fmul_rn(-0.2f, c2));
        float vd2 = __fadd_rn(v2, __fmul_rn(0.1f, __fadd_rn(__fsub_rn(0.f, v2), c2)));
        float id3 = __fadd_rn(c3, __fmul_rn(-0.2f, c3));
        float vd3 = __fadd_rn(v3, __fmul_rn(0.1f, __fadd_rn(__fsub_rn(0.f, v3), c3)));
        int z0 = __fsub_rn(vd0, 1.0f) > 0.f;
        int z1 = __fsub_rn(vd1, 1.0f) > 0.f;
        int z2 = __fsub_rn(vd2, 1.0f) > 0.f;
        int z3 = __fsub_rn(vd3, 1.0f) > 0.f;
        v0 = z0 ? 0.f : vd0;  v1 = z1 ? 0.f : vd1;
        v2 = z2 ? 0.f : vd2;  v3 = z3 ? 0.f : vd3;
        c0 = __fadd_rn(__fadd_rn(id0, __fsub_rn(xc0, inh0)), rec0);
        c1 = __fadd_rn(__fadd_rn(id1, __fsub_rn(xc1, inh1)), rec1);
        c2 = __fadd_rn(__fadd_rn(id2, __fsub_rn(xc2, inh2)), rec2);
        c3 = __fadd_rn(__fadd_rn(id3, __fsub_rn(xc3, inh3)), rec3);

        float* orow = out + ((size_t)st * BN + b) * EN;
        orow[t]        = z0 ? 1.f : 0.f;
        orow[t + 512]  = z1 ? 1.f : 0.f;
        orow[t + 1024] = z2 ? 1.f : 0.f;
        orow[t + 1536] = z3 ? 1.f : 0.f;

        // shift x pipeline; prefetch st+2
        xc0 = xn0; xc1 = xn1; xc2 = xn2; xc3 = xn3;
        if (st + 2 < TN) {
            const float* xb = x + ((size_t)(st + 2) * BN + b) * EN;
            xn0 = xb[t]; xn1 = xb[t + 512]; xn2 = xb[t + 1024]; xn3 = xb[t + 1536];
        }

        // inhibitory decay + spike from OLD inh state
        float ii_dec = __fadd_rn(ii, __fmul_rn(-0.2f, ii));
        float vi_dec = __fadd_rn(iv, __fmul_rn(0.1f, __fadd_rn(__fsub_rn(0.f, iv), ii)));
        int zi = __fsub_rn(vi_dec, 1.0f) > 0.f;   // t>=256: state stays 0 -> zi=0
        iv = zi ? 0.f : vi_dec;

        int stable = g_ok && z0 && z1 && z2 && z3
                   && (c0 >= 64.f) && (c1 >= 64.f) && (c2 >= 64.f) && (c3 >= 64.f);

        // ---- [c] publish spikes + per-warp flag & count bytes ----
        uint32_t eb0 = __ballot_sync(0xffffffffu, z0);
        uint32_t eb1 = __ballot_sync(0xffffffffu, z1);
        uint32_t eb2 = __ballot_sync(0xffffffffu, z2);
        uint32_t eb3 = __ballot_sync(0xffffffffu, z3);
        uint32_t ibal = __ballot_sync(0xffffffffu, zi);
        uint32_t sbal = __ballot_sync(0xffffffffu, stable);
        if (lane == 0) {
            s_ez[wp][warp]      = eb0;
            s_ez[wp][16 + warp] = eb1;
            s_ez[wp][32 + warp] = eb2;
            s_ez[wp][48 + warp] = eb3;
            uint32_t ea = ((eb0 & eb1 & eb2 & eb3) == 0xffffffffu) ? 1u : 0u;
            uint32_t ey = ((eb0 | eb1 | eb2 | eb3) != 0u) ? 1u : 0u;
            uint32_t sa = (sbal == 0xffffffffu) ? 1u : 0u;
            uint32_t ia, iy;
            if (warp < IWORDS) {
                s_iz[wp][warp] = ibal;
                ia = (ibal == 0xffffffffu) ? 1u : 0u;
                iy = (ibal != 0u) ? 1u : 0u;
            } else { ia = 1u; iy = 0u; }
            s_fb[wp][warp]  = (unsigned char)(ea | (ey << 1) | (ia << 2) | (iy << 3) | (sa << 4));
            s_cnt[wp][warp] = (unsigned char)(__popc(eb0) + __popc(eb1) + __popc(eb2) + __popc(eb3));
        }
        __syncthreads();   // the only barrier per step

        uint4 f = *reinterpret_cast<const uint4*>(&s_fb[wp][0]);
        uint32_t fand = f.x & f.y & f.z & f.w;
        uint32_t forr = f.x | f.y | f.z | f.w;
        fand &= fand >> 16; fand &= fand >> 8;
        forr |= forr >> 16; forr |= forr >> 8;
        int ne_all = fand & 1;        int ne_any = (forr >> 1) & 1;
        int ni_all = (fand >> 2) & 1; int ni_any = (forr >> 3) & 1;

        if ((fand >> 4) & 1) { ts = st + 1; break; }   // absorbing saturation (uniform)

        uint4 cc = *reinterpret_cast<const uint4*>(&s_cnt[wp][0]);
        unsigned int ec = 0u;
        ec = __dp4a(cc.x, 0x01010101u, ec); ec = __dp4a(cc.y, 0x01010101u, ec);
        ec = __dp4a(cc.z, 0x01010101u, ec); ec = __dp4a(cc.w, 0x01010101u, ec);
        int ecnt = (int)ec;

        // ---- [d] inhibitory current update with NEW exc spikes ----
        // COALESCED select-dense over original wei[e][i] (exact ascending-e chain)
        if (t < IN_) {
            float xi;
            if (ne_all)       xi = cwei;
            else if (!ne_any) xi = 0.f;
            else if (ecnt <= 24) {
                xi = 0.f;   // exact ascending-e scan, bounded iterations, coalesced
                for (int w = 0; w < EWORDS; w++) {
                    uint32_t m = s_ez[wp][w];
                    while (m) {
                        int r = __ffs(m) - 1; m &= m - 1;
                        xi = __fadd_rn(xi, wei[(size_t)(w * 32 + r) * IN_ + t]);
                    }
                }
            } else {
                // fixed 2048-trip select-dense: unconditional coalesced loads,
                // fadd(s, +0.0f) == s bit-exactly (all terms >= 0)
                xi = 0.f;
                for (int w = 0; w < EWORDS; w++) {
                    uint32_t m = s_ez[wp][w];
#pragma unroll 8
                    for (int k = 0; k < 32; k++) {
                        float wv = wei[(size_t)(w * 32 + k) * IN_ + t];
                        xi = __fadd_rn(xi, ((m >> k) & 1u) ? wv : 0.0f);
                    }
                }
            }
            ii = __fadd_rn(ii_dec, xi);
        }
        pe_all = ne_all; pe_any = ne_any; pi_all = ni_all; pi_any = ni_any;
    }

    // ---- fused fill: rows [ts, TN) of this batch are all ones ----
    const float4 ones = make_float4(1.f, 1.f, 1.f, 1.f);
    for (int r = ts; r < TN; r++) {
        float4* o4 = reinterpret_cast<float4*>(out + ((size_t)r * BN + b) * EN);
        __stcs(&o4[t], ones);   // 512 threads x 16B = full 2048-float row
    }
}

extern "C" void kernel_launch(void* const* d_in, const int* in_sizes, int n_in,
                              void* d_out, int out_size)
{
    const float* x     = (const float*)d_in[0];  // [T,B,E]
    // d_in[1] = w_in (identity) -- exact pass-through, unused
    const float* w_rec = (const float*)d_in[2];  // [E,E]
    const float* w_ei  = (const float*)d_in[3];  // [E,I]
    const float* w_ie  = (const float*)d_in[4];  // [I,E]
    float* out = (float*)d_out;

    prep1<<<1024, 256>>>(w_rec, w_ie);
    prep2<<<9 + 256, 256>>>(x, w_ei);
    sim_kernel<<<BN, NT>>>(x, w_ei, out);
}

// round 15
// speedup vs baseline: 1.6360x; 1.6360x over previous
#include <cuda_runtime.h>
#include <cstdint>

#define EN 2048
#define IN_ 256
#define TN 256
#define BN 32
#define EWORDS 64
#define IWORDS 8
#define NT 512      // threads per CTA; thread t owns exc neurons t, t+512, t+1024, t+1536

// c-order: c(j) = 4*(j&511) + (j>>9)  <->  j(c) = (c>>2) + 512*(c&3)
// thread t's 4 neurons occupy c = 4t..4t+3  -> float4/uint4 loads.

__device__ __align__(16) uint32_t g_wrecP[EWORDS * EN];  // [w][c] packed w_rec bits (512KB)
__device__ __align__(16) float    g_wieP[IN_ * EN];      // [i][c] = w_ie[i][j(c)]  (2MB)
__device__ __align__(16) float    g_rowsumP[EN];         // [c] popcount of w_rec row j(c)
__device__ __align__(16) float    g_cs_wieP[EN];         // [c] sum_i w_ie[i][j(c)] (ascending i)
__device__ float    g_cs_wei[IN_];                       // [i] sum_e w_ei[e][i] (ascending e)
__device__ int      g_rsmin;
__device__ uint32_t g_cwie_max_u, g_xmax_u;

// ---------------- prep 1: pack/permute weights + reset markers ----------------
__global__ void prep1(const float* __restrict__ wrec,
                      const float* __restrict__ wie) {
    const int bid = blockIdx.x, tid = threadIdx.x;
    if (bid == 0 && tid == 0) {
        g_rsmin = 0x7fffffff;
        g_cwie_max_u = 0u;
        g_xmax_u = 0u;
    }
    if (bid < 512) {
        // A: pack w_rec -> wrecP.  idx = j*64 + w
        int idx = bid * 256 + tid;
        int j = idx >> 6, w = idx & 63;
        const uint4* p = reinterpret_cast<const uint4*>(wrec + (size_t)j * EN + (size_t)w * 32);
        uint32_t m = 0;
#pragma unroll
        for (int k = 0; k < 8; k++) {
            uint4 f = p[k];   // entries exactly 0.0f or 1.0f
            m |= (f.x ? 1u : 0u) << (k * 4 + 0);
            m |= (f.y ? 1u : 0u) << (k * 4 + 1);
            m |= (f.z ? 1u : 0u) << (k * 4 + 2);
            m |= (f.w ? 1u : 0u) << (k * 4 + 3);
        }
        int c = 4 * (j & 511) + (j >> 9);
        g_wrecP[w * EN + c] = m;
    } else {
        // B: permute w_ie -> wieP. u enumerates (i, j-group of 4)
        int u = (bid - 512) * 256 + tid;         // 0..131071
        int i = u >> 9, jq = u & 511;
        float4 f = reinterpret_cast<const float4*>(wie + (size_t)i * EN)[jq];
        int j0 = 4 * jq;
        float vals[4] = {f.x, f.y, f.z, f.w};
#pragma unroll
        for (int q = 0; q < 4; q++) {
            int j = j0 + q;
            int c = 4 * (j & 511) + (j >> 9);
            g_wieP[(size_t)i * EN + c] = vals[q];
        }
    }
}

// ---------------- prep 2: sums + invariant bounds + max|x| ----------------
__global__ void prep2(const float* __restrict__ x, const float* __restrict__ wei) {
    const int bid = blockIdx.x, tid = threadIdx.x, lane = tid & 31;
    if (bid < 8) {
        int c = bid * 256 + tid;  // c-order index 0..2047
        int cnt = 0;
#pragma unroll 8
        for (int w = 0; w < EWORDS; w++) cnt += __popc(g_wrecP[w * EN + c]);
        g_rowsumP[c] = (float)cnt;
        atomicMin(&g_rsmin, cnt);
        float s = 0.f;
#pragma unroll 4
        for (int i = 0; i < IN_; i++) s = __fadd_rn(s, g_wieP[(size_t)i * EN + c]);
        g_cs_wieP[c] = s;
        atomicMax(&g_cwie_max_u, __float_as_uint(s));  // s >= 0: bits monotone
    } else if (bid == 8) {
        // cs_wei[i] = sum_e wei[e][i], ascending e, exact chain; coalesced across i
        if (tid < IN_) {
            float q = 0.f;
#pragma unroll 4
            for (int e = 0; e < EN; e++)
                q = __fadd_rn(q, wei[(size_t)e * IN_ + tid]);
            g_cs_wei[tid] = q;
        }
    } else {
        const float4* x4 = reinterpret_cast<const float4*>(x);
        const int n4 = (TN * BN * EN) / 4;
        int i = (bid - 9) * 256 + tid;
        const int stride = 256 * 256;
        float m = 0.f;
        for (; i < n4; i += stride) {
            float4 f = x4[i];
            m = fmaxf(m, fmaxf(fmaxf(fabsf(f.x), fabsf(f.y)), fmaxf(fabsf(f.z), fabsf(f.w))));
        }
#pragma unroll
        for (int off = 16; off > 0; off >>= 1)
            m = fmaxf(m, __shfl_xor_sync(0xffffffffu, m, off));
        if (lane == 0) atomicMax(&g_xmax_u, __float_as_uint(m));
    }
}

// ---------------- main simulator: one CTA per batch, list-based count-proportional gathers ----
__global__ __launch_bounds__(NT, 1)
void sim_kernel(const float* __restrict__ x,
                const float* __restrict__ wei,
                float* __restrict__ out)
{
    __shared__ uint32_t s_ez[2][EWORDS];
    __shared__ uint32_t s_iz[2][IWORDS];
    __shared__ __align__(16) unsigned char s_fb[2][16];
    __shared__ __align__(16) unsigned char s_cnt[2][16];
    __shared__ uint16_t s_elist[2][1024];   // ez spiker OR complement indices (ascending e)
    __shared__ uint16_t s_ilist[2][IN_];    // iz spiker indices (ascending i)

    const int t    = threadIdx.x;
    const int b    = blockIdx.x;
    const int warp = t >> 5, lane = t & 31;

    float v0 = 0.f, v1 = 0.f, v2 = 0.f, v3 = 0.f;
    float c0 = 0.f, c1 = 0.f, c2 = 0.f, c3 = 0.f;
    float iv = 0.f, ii = 0.f;                      // inh neuron t (t < 256)

    const float cwei = (t < IN_) ? g_cs_wei[t] : 0.f;

    // absorbing-saturation invariant (exc-only, proven sufficient; see R8):
    const int g_ok =
        __fadd_rn((float)g_rsmin,
                  -__fadd_rn(__uint_as_float(g_cwie_max_u), __uint_as_float(g_xmax_u))) >= 13.0f;

    const uint4*  wrecP4 = reinterpret_cast<const uint4*>(g_wrecP);    // [w*512 + t]
    const float4* wieP4  = reinterpret_cast<const float4*>(g_wieP);    // [i*512 + t]
    const float4* rsP4   = reinterpret_cast<const float4*>(g_rowsumP);
    const float4* cwP4   = reinterpret_cast<const float4*>(g_cs_wieP);

    if (t < EWORDS) s_ez[1][t] = 0u;
    if (t < IWORDS) s_iz[1][t] = 0u;
    __syncthreads();

    int pe_all = 0, pe_any = 0, pi_all = 0, pi_any = 0;
    int p_ecnt = 0;   // previous step's exc spike count (uniform)
    int ts = TN;

    // depth-2 x pipeline
    float xc0 = x[(size_t)b * EN + t];
    float xc1 = x[(size_t)b * EN + t + 512];
    float xc2 = x[(size_t)b * EN + t + 1024];
    float xc3 = x[(size_t)b * EN + t + 1536];
    float xn0 = x[((size_t)1 * BN + b) * EN + t];
    float xn1 = x[((size_t)1 * BN + b) * EN + t + 512];
    float xn2 = x[((size_t)1 * BN + b) * EN + t + 1024];
    float xn3 = x[((size_t)1 * BN + b) * EN + t + 1536];

    for (int st = 0; st < TN; st++) {
        const int wp = st & 1, rp = wp ^ 1;

        // ---- [a] recurrent term (integer-exact popcount, dense) ----
        float rec0, rec1, rec2, rec3;
        if (pe_all) {
            float4 r = rsP4[t];
            rec0 = r.x; rec1 = r.y; rec2 = r.z; rec3 = r.w;
        } else if (!pe_any) {
            rec0 = rec1 = rec2 = rec3 = 0.f;
        } else {
            int a0 = 0, a1 = 0, a2 = 0, a3 = 0;
#pragma unroll 8
            for (int w = 0; w < EWORDS; w++) {
                uint32_t m = s_ez[rp][w];
                uint4 q = wrecP4[w * 512 + t];
                a0 += __popc(m & q.x); a1 += __popc(m & q.y);
                a2 += __popc(m & q.z); a3 += __popc(m & q.w);
            }
            rec0 = (float)a0; rec1 = (float)a1; rec2 = (float)a2; rec3 = (float)a3;
        }

        // ---- [a] inhibitory feedback via iz list (exact ascending-i chains) ----
        float inh0, inh1, inh2, inh3;
        if (pi_all) {
            float4 cwv = cwP4[t];
            inh0 = cwv.x; inh1 = cwv.y; inh2 = cwv.z; inh3 = cwv.w;
        } else if (!pi_any) {
            inh0 = inh1 = inh2 = inh3 = 0.f;
        } else {
            uint4 ma = *reinterpret_cast<const uint4*>(&s_iz[rp][0]);
            uint4 mb = *reinterpret_cast<const uint4*>(&s_iz[rp][4]);
            int icnt = __popc(ma.x) + __popc(ma.y) + __popc(ma.z) + __popc(ma.w)
                     + __popc(mb.x) + __popc(mb.y) + __popc(mb.z) + __popc(mb.w);
            inh0 = inh1 = inh2 = inh3 = 0.f;
#pragma unroll 4
            for (int k = 0; k < icnt; k++) {
                int i = s_ilist[rp][k];
                float4 wv = wieP4[i * 512 + t];
                inh0 = __fadd_rn(inh0, wv.x); inh1 = __fadd_rn(inh1, wv.y);
                inh2 = __fadd_rn(inh2, wv.z); inh3 = __fadd_rn(inh3, wv.w);
            }
        }

        // ---- [b] excitatory update (JAX-exact rounding order) ----
        float id0 = __fadd_rn(c0, __fmul_rn(-0.2f, c0));
        float vd0 = __fadd_rn(v0, __fmul_rn(0.1f, __fadd_rn(__fsub_rn(0.f, v0), c0)));
        float id1 = __fadd_rn(c1, __fmul_rn(-0.2f, c1));
        float vd1 = __fadd_rn(v1, __fmul_rn(0.1f, __fadd_rn(__fsub_rn(0.f, v1), c1)));
        float id2 = __fadd_rn(c2, __fmul_rn(-0.2f, c2));
        float vd2 = __fadd_rn(v2, __fmul_rn(0.1f, __fadd_rn(__fsub_rn(0.f, v2), c2)));
        float id3 = __fadd_rn(c3, __fmul_rn(-0.2f, c3));
        float vd3 = __fadd_rn(v3, __fmul_rn(0.1f, __fadd_rn(__fsub_rn(0.f, v3), c3)));
        int z0 = __fsub_rn(vd0, 1.0f) > 0.f;
        int z1 = __fsub_rn(vd1, 1.0f) > 0.f;
        int z2 = __fsub_rn(vd2, 1.0f) > 0.f;
        int z3 = __fsub_rn(vd3, 1.0f) > 0.f;
        v0 = z0 ? 0.f : vd0;  v1 = z1 ? 0.f : vd1;
        v2 = z2 ? 0.f : vd2;  v3 = z3 ? 0.f : vd3;
        c0 = __fadd_rn(__fadd_rn(id0, __fsub_rn(xc0, inh0)), rec0);
        c1 = __fadd_rn(__fadd_rn(id1, __fsub_rn(xc1, inh1)), rec1);
        c2 = __fadd_rn(__fadd_rn(id2, __fsub_rn(xc2, inh2)), rec2);
        c3 = __fadd_rn(__fadd_rn(id3, __fsub_rn(xc3, inh3)), rec3);

        float* orow = out + ((size_t)st * BN + b) * EN;
        orow[t]        = z0 ? 1.f : 0.f;
        orow[t + 512]  = z1 ? 1.f : 0.f;
        orow[t + 1024] = z2 ? 1.f : 0.f;
        orow[t + 1536] = z3 ? 1.f : 0.f;

        // shift x pipeline; prefetch st+2
        xc0 = xn0; xc1 = xn1; xc2 = xn2; xc3 = xn3;
        if (st + 2 < TN) {
            const float* xb = x + ((size_t)(st + 2) * BN + b) * EN;
            xn0 = xb[t]; xn1 = xb[t + 512]; xn2 = xb[t + 1024]; xn3 = xb[t + 1536];
        }

        // inhibitory decay + spike from OLD inh state
        float ii_dec = __fadd_rn(ii, __fmul_rn(-0.2f, ii));
        float vi_dec = __fadd_rn(iv, __fmul_rn(0.1f, __fadd_rn(__fsub_rn(0.f, iv), ii)));
        int zi = __fsub_rn(vi_dec, 1.0f) > 0.f;   // t>=256: state stays 0 -> zi=0
        iv = zi ? 0.f : vi_dec;

        int stable = g_ok && z0 && z1 && z2 && z3
                   && (c0 >= 64.f) && (c1 >= 64.f) && (c2 >= 64.f) && (c3 >= 64.f);

        // ---- [c] publish spikes + per-warp flag & count bytes ----
        uint32_t eb0 = __ballot_sync(0xffffffffu, z0);
        uint32_t eb1 = __ballot_sync(0xffffffffu, z1);
        uint32_t eb2 = __ballot_sync(0xffffffffu, z2);
        uint32_t eb3 = __ballot_sync(0xffffffffu, z3);
        uint32_t ibal = __ballot_sync(0xffffffffu, zi);
        uint32_t sbal = __ballot_sync(0xffffffffu, stable);
        if (lane == 0) {
            s_ez[wp][warp]      = eb0;
            s_ez[wp][16 + warp] = eb1;
            s_ez[wp][32 + warp] = eb2;
            s_ez[wp][48 + warp] = eb3;
            uint32_t ea = ((eb0 & eb1 & eb2 & eb3) == 0xffffffffu) ? 1u : 0u;
            uint32_t ey = ((eb0 | eb1 | eb2 | eb3) != 0u) ? 1u : 0u;
            uint32_t sa = (sbal == 0xffffffffu) ? 1u : 0u;
            uint32_t ia, iy;
            if (warp < IWORDS) {
                s_iz[wp][warp] = ibal;
                ia = (ibal == 0xffffffffu) ? 1u : 0u;
                iy = (ibal != 0u) ? 1u : 0u;
            } else { ia = 1u; iy = 0u; }
            s_fb[wp][warp]  = (unsigned char)(ea | (ey << 1) | (ia << 2) | (iy << 3) | (sa << 4));
            s_cnt[wp][warp] = (unsigned char)(__popc(eb0) + __popc(eb1) + __popc(eb2) + __popc(eb3));
        }
        __syncthreads();   // barrier 1: spikes & counts visible

        uint4 f = *reinterpret_cast<const uint4*>(&s_fb[wp][0]);
        uint32_t fand = f.x & f.y & f.z & f.w;
        uint32_t forr = f.x | f.y | f.z | f.w;
        fand &= fand >> 16; fand &= fand >> 8;
        forr |= forr >> 16; forr |= forr >> 8;
        int ne_all = fand & 1;        int ne_any = (forr >> 1) & 1;
        int ni_all = (fand >> 2) & 1; int ni_any = (forr >> 3) & 1;

        if ((fand >> 4) & 1) { ts = st + 1; break; }   // absorbing saturation (uniform)

        uint4 cc = *reinterpret_cast<const uint4*>(&s_cnt[wp][0]);
        unsigned int ec = 0u;
        ec = __dp4a(cc.x, 0x01010101u, ec); ec = __dp4a(cc.y, 0x01010101u, ec);
        ec = __dp4a(cc.z, 0x01010101u, ec); ec = __dp4a(cc.w, 0x01010101u, ec);
        int ecnt = (int)ec;   // uniform across all threads

        // ---- list build: warp 0 = ez (smaller of spikers/complement, ascending e);
        //                  warp 1 = iz spikers (ascending i) ----
        if (warp == 0) {
            if (ne_any && !ne_all) {
                uint32_t w0 = s_ez[wp][2 * lane], w1 = s_ez[wp][2 * lane + 1];
                if (ecnt > 1024) { w0 = ~w0; w1 = ~w1; }
                int cnt = __popc(w0) + __popc(w1);
                int off = cnt;
#pragma unroll
                for (int d = 1; d < 32; d <<= 1) {
                    int nn = __shfl_up_sync(0xffffffffu, off, d);
                    if (lane >= d) off += nn;
                }
                off -= cnt;    // exclusive prefix
                int base_e = lane * 64;
                while (w0) { int r = __ffs(w0) - 1; w0 &= w0 - 1;
                             s_elist[wp][off++] = (uint16_t)(base_e + r); }
                base_e += 32;
                while (w1) { int r = __ffs(w1) - 1; w1 &= w1 - 1;
                             s_elist[wp][off++] = (uint16_t)(base_e + r); }
            }
        } else if (warp == 1) {
            if (ni_any && !ni_all) {
                uint32_t m0 = (lane < IWORDS) ? s_iz[wp][lane] : 0u;
                int cnt = __popc(m0);
                int off = cnt;
#pragma unroll
                for (int d = 1; d < 32; d <<= 1) {
                    int nn = __shfl_up_sync(0xffffffffu, off, d);
                    if (lane >= d) off += nn;
                }
                off -= cnt;
                int base_i = lane * 32;
                while (m0) { int r = __ffs(m0) - 1; m0 &= m0 - 1;
                             s_ilist[wp][off++] = (uint16_t)(base_i + r); }
            }
        }
        __syncthreads();   // barrier 2: lists visible

        // ---- [d] inhibitory current update via ez list (count-proportional) ----
        if (t < IN_) {
            float xi;
            if (ne_all)       xi = cwei;
            else if (!ne_any) xi = 0.f;
            else {
                int n = (ecnt <= 1024) ? ecnt : (EN - ecnt);
                float s = 0.f;
#pragma unroll 4
                for (int k = 0; k < n; k++) {
                    int e = s_elist[wp][k];
                    s = __fadd_rn(s, wei[(size_t)e * IN_ + t]);
                }
                xi = (ecnt <= 1024) ? s : __fsub_rn(cwei, s);
            }
            ii = __fadd_rn(ii_dec, xi);
        }
        pe_all = ne_all; pe_any = ne_any; pi_all = ni_all; pi_any = ni_any;
        p_ecnt = ecnt;
        (void)p_ecnt;
    }

    // ---- fused fill: rows [ts, TN) of this batch are all ones ----
    const float4 ones = make_float4(1.f, 1.f, 1.f, 1.f);
    for (int r = ts; r < TN; r++) {
        float4* o4 = reinterpret_cast<float4*>(out + ((size_t)r * BN + b) * EN);
        __stcs(&o4[t], ones);   // 512 threads x 16B = full 2048-float row
    }
}

extern "C" void kernel_launch(void* const* d_in, const int* in_sizes, int n_in,
                              void* d_out, int out_size)
{
    const float* x     = (const float*)d_in[0];  // [T,B,E]
    // d_in[1] = w_in (identity) -- exact pass-through, unused
    const float* w_rec = (const float*)d_in[2];  // [E,E]
    const float* w_ei  = (const float*)d_in[3];  // [E,I]
    const float* w_ie  = (const float*)d_in[4];  // [I,E]
    float* out = (float*)d_out;

    prep1<<<1024, 256>>>(w_rec, w_ie);
    prep2<<<9 + 256, 256>>>(x, w_ei);
    sim_kernel<<<BN, NT>>>(x, w_ei, out);
}

// round 16
// speedup vs baseline: 1.7799x; 1.0880x over previous
#include <cuda_runtime.h>
#include <cstdint>

#define EN 2048
#define IN_ 256
#define TN 256
#define BN 32
#define EWORDS 64
#define IWORDS 8
#define NT 512
#define CLN 4    // CTAs per cluster; batch = cluster

// packed w_rec, sim-load-friendly layout: g_wrecC[((j>>9)*16+g)*512 + (j&511)]
// = words [4g..4g+3] of row j (bit e&31 of word e>>5 = w_rec[j][e] != 0)
__device__ __align__(16) uint4 g_wrecC[EN * 16];   // 512KB
__device__ float g_rowsum[EN];    // exact popcount of row j
__device__ float g_cs_wie[EN];    // sum_i w_ie[i][j] (ascending i)
__device__ float g_cs_wei[IN_];   // sum_e w_ei[e][i] (ascending e)
__device__ int      g_rsmin;
__device__ uint32_t g_cwie_max_u, g_xmax_u;

// ---------------- prep 1: pack w_rec + reset markers ----------------
__global__ void prep1(const float* __restrict__ wrec) {
    if (blockIdx.x == 0 && threadIdx.x == 0) {
        g_rsmin = 0x7fffffff; g_cwie_max_u = 0u; g_xmax_u = 0u;
    }
    int idx = blockIdx.x * 256 + threadIdx.x;   // 32768 tasks: (j, g)
    int j = idx >> 4, g = idx & 15;
    const uint4* p = reinterpret_cast<const uint4*>(wrec + (size_t)j * EN + g * 128);
    uint32_t wd[4];
#pragma unroll
    for (int w4 = 0; w4 < 4; w4++) {
        uint32_t m = 0;
#pragma unroll
        for (int k = 0; k < 8; k++) {
            uint4 f = p[w4 * 8 + k];   // entries exactly 0.0f or 1.0f
            m |= (f.x ? 1u : 0u) << (k * 4 + 0);
            m |= (f.y ? 1u : 0u) << (k * 4 + 1);
            m |= (f.z ? 1u : 0u) << (k * 4 + 2);
            m |= (f.w ? 1u : 0u) << (k * 4 + 3);
        }
        wd[w4] = m;
    }
    g_wrecC[((j >> 9) * 16 + g) * 512 + (j & 511)] = make_uint4(wd[0], wd[1], wd[2], wd[3]);
}

// ---------------- prep 2: sums + invariant bounds + max|x| ----------------
__global__ void prep2(const float* __restrict__ x,
                      const float* __restrict__ wie,
                      const float* __restrict__ wei) {
    const int bid = blockIdx.x, tid = threadIdx.x, lane = tid & 31;
    if (bid < 8) {
        int j = bid * 256 + tid;
        int r = j >> 9, tt = j & 511;
        int cnt = 0;
#pragma unroll
        for (int g = 0; g < 16; g++) {
            uint4 q = g_wrecC[(r * 16 + g) * 512 + tt];
            cnt += __popc(q.x) + __popc(q.y) + __popc(q.z) + __popc(q.w);
        }
        g_rowsum[j] = (float)cnt;
        atomicMin(&g_rsmin, cnt);
        float s = 0.f;
#pragma unroll 4
        for (int i = 0; i < IN_; i++) s = __fadd_rn(s, wie[(size_t)i * EN + j]);
        g_cs_wie[j] = s;
        atomicMax(&g_cwie_max_u, __float_as_uint(s));  // s >= 0: bits monotone
    } else if (bid == 8) {
        if (tid < IN_) {
            float q = 0.f;
#pragma unroll 4
            for (int e = 0; e < EN; e++) q = __fadd_rn(q, wei[(size_t)e * IN_ + tid]);
            g_cs_wei[tid] = q;
        }
    } else {
        const float4* x4 = reinterpret_cast<const float4*>(x);
        const int n4 = (TN * BN * EN) / 4;
        int i = (bid - 9) * 256 + tid;
        const int stride = 256 * 256;
        float m = 0.f;
        for (; i < n4; i += stride) {
            float4 f = x4[i];
            m = fmaxf(m, fmaxf(fmaxf(fabsf(f.x), fabsf(f.y)), fmaxf(fabsf(f.z), fabsf(f.w))));
        }
#pragma unroll
        for (int off = 16; off > 0; off >>= 1)
            m = fmaxf(m, __shfl_xor_sync(0xffffffffu, m, off));
        if (lane == 0) atomicMax(&g_xmax_u, __float_as_uint(m));
    }
}

// ---------------- cluster helpers ----------------
__device__ __forceinline__ uint32_t smem_u32(const void* p) {
    uint32_t a;
    asm("{ .reg .u64 t; cvta.to.shared.u64 t, %1; cvt.u32.u64 %0, t; }" : "=r"(a) : "l"(p));
    return a;
}
__device__ __forceinline__ void stc_u32(uint32_t la, uint32_t rk, uint32_t v) {
    uint32_t ra;
    asm volatile("mapa.shared::cluster.u32 %0, %1, %2;" : "=r"(ra) : "r"(la), "r"(rk));
    asm volatile("st.shared::cluster.u32 [%0], %1;" :: "r"(ra), "r"(v) : "memory");
}
__device__ __forceinline__ void stc_u16(uint32_t la, uint32_t rk, uint16_t v) {
    uint32_t ra;
    asm volatile("mapa.shared::cluster.u32 %0, %1, %2;" : "=r"(ra) : "r"(la), "r"(rk));
    asm volatile("st.shared::cluster.u16 [%0], %1;" :: "r"(ra), "h"(v) : "memory");
}

// ---------------- main simulator: 4-CTA cluster per batch, wrec in SMEM ----------------
__global__ void __cluster_dims__(CLN, 1, 1) __launch_bounds__(NT, 1)
sim_kernel(const float* __restrict__ x,
           const float* __restrict__ wei,
           const float* __restrict__ wie,
           float* __restrict__ out)
{
    extern __shared__ __align__(16) uint4 s_wrec[];   // [16][512] = 128KB (this CTA's rows)
    __shared__ __align__(16) uint32_t s_ez[2][EWORDS];
    __shared__ __align__(16) uint32_t s_iz[2][IWORDS];
    __shared__ __align__(16) uint16_t s_fc[2][64];    // per-warp (flags | count<<8), cluster-wide
    __shared__ uint16_t s_elist[2][1024];
    __shared__ uint16_t s_ilist[2][IN_];

    const int t = threadIdx.x;
    const int warp = t >> 5, lane = t & 31;
    const int b = blockIdx.x >> 2;           // cluster index = batch
    uint32_t rank;
    asm("mov.u32 %0, %%cluster_ctarank;" : "=r"(rank));
    const int j  = (int)rank * 512 + t;      // this thread's exc neuron
    const int i0 = (int)rank * 64 + t;       // this thread's inh neuron (t < 64)

    // load this CTA's w_rec quarter into SMEM (conflict-free [g][t] layout)
#pragma unroll
    for (int g = 0; g < 16; g++)
        s_wrec[g * 512 + t] = g_wrecC[((int)rank * 16 + g) * 512 + t];

    float v = 0.f, cu = 0.f, iv = 0.f, ii = 0.f;
    const float rs   = g_rowsum[j];
    const float cw   = g_cs_wie[j];
    const float cwei = (t < 64) ? g_cs_wei[i0] : 0.f;
    // absorbing-saturation invariant (exc-only, proven sufficient; see R8)
    const int g_ok =
        __fadd_rn((float)g_rsmin,
                  -__fadd_rn(__uint_as_float(g_cwie_max_u), __uint_as_float(g_xmax_u))) >= 13.0f;

    if (t < EWORDS) s_ez[1][t] = 0u;
    if (t < IWORDS) s_iz[1][t] = 0u;
    __syncthreads();

    int pe_all = 0, pe_any = 0, pi_all = 0, pi_any = 0;
    int ts = TN;

    // depth-2 x pipeline (1 scalar per thread)
    float xc = x[(size_t)b * EN + j];
    float xn = x[((size_t)1 * BN + b) * EN + j];

    for (int st = 0; st < TN; st++) {
        const int wp = st & 1, rp = wp ^ 1;

        // ---- [a] recurrent term: SMEM popcount (integer-exact) ----
        float rec;
        if (pe_all)       rec = rs;
        else if (!pe_any) rec = 0.f;
        else {
            int a = 0;
#pragma unroll
            for (int g = 0; g < 16; g++) {
                uint4 q = s_wrec[g * 512 + t];
                uint4 m = *reinterpret_cast<const uint4*>(&s_ez[rp][4 * g]);
                a += __popc(m.x & q.x) + __popc(m.y & q.y)
                   + __popc(m.z & q.z) + __popc(m.w & q.w);
            }
            rec = (float)a;
        }

        // ---- [a] inhibitory feedback via iz list (exact ascending-i chain, coalesced) ----
        float inh;
        if (pi_all)       inh = cw;
        else if (!pi_any) inh = 0.f;
        else {
            int icnt = 0;
#pragma unroll
            for (int w = 0; w < IWORDS; w++) icnt += __popc(s_iz[rp][w]);
            float s = 0.f;
#pragma unroll 4
            for (int k = 0; k < icnt; k++) {
                int i = s_ilist[rp][k];
                s = __fadd_rn(s, wie[(size_t)i * EN + j]);
            }
            inh = s;
        }

        // ---- [b] excitatory update (JAX-exact rounding order) ----
        float id = __fadd_rn(cu, __fmul_rn(-0.2f, cu));
        float vd = __fadd_rn(v, __fmul_rn(0.1f, __fadd_rn(__fsub_rn(0.f, v), cu)));
        int z = __fsub_rn(vd, 1.0f) > 0.f;
        v = z ? 0.f : vd;
        cu = __fadd_rn(__fadd_rn(id, __fsub_rn(xc, inh)), rec);
        out[((size_t)st * BN + b) * EN + j] = z ? 1.f : 0.f;

        xc = xn;
        if (st + 2 < TN) xn = x[((size_t)(st + 2) * BN + b) * EN + j];

        // inhibitory decay + spike from OLD inh state (t>=64: stays 0)
        float ii_dec = __fadd_rn(ii, __fmul_rn(-0.2f, ii));
        float vi_dec = __fadd_rn(iv, __fmul_rn(0.1f, __fadd_rn(__fsub_rn(0.f, iv), ii)));
        int zi = __fsub_rn(vi_dec, 1.0f) > 0.f;
        iv = zi ? 0.f : vi_dec;

        int stable = g_ok && z && (cu >= 64.f);

        // ---- [c] publish ballots + fused flag/count to ALL cluster CTAs ----
        uint32_t eb   = __ballot_sync(0xffffffffu, z);
        uint32_t ibal = __ballot_sync(0xffffffffu, zi);
        uint32_t sbal = __ballot_sync(0xffffffffu, stable);
        if (lane == 0) {
            uint32_t ea = (eb == 0xffffffffu) ? 1u : 0u;
            uint32_t ey = (eb != 0u) ? 1u : 0u;
            uint32_t sa = (sbal == 0xffffffffu) ? 1u : 0u;
            uint32_t ia, iy;
            if (warp < 2) { ia = (ibal == 0xffffffffu) ? 1u : 0u; iy = (ibal != 0u) ? 1u : 0u; }
            else          { ia = 1u; iy = 0u; }
            uint16_t fc = (uint16_t)((ea | (ey << 1) | (ia << 2) | (iy << 3) | (sa << 4))
                                     | ((uint32_t)__popc(eb) << 8));
            uint32_t la_ez = smem_u32(&s_ez[wp][rank * 16 + warp]);
            uint32_t la_fc = smem_u32(&s_fc[wp][rank * 16 + warp]);
            uint32_t la_iz = smem_u32(&s_iz[wp][rank * 2 + warp]);
#pragma unroll
            for (uint32_t pr = 0; pr < CLN; pr++) {
                stc_u32(la_ez, pr, eb);
                stc_u16(la_fc, pr, fc);
                if (warp < 2) stc_u32(la_iz, pr, ibal);
            }
        }
        // one cluster barrier per step: publishes all remote stores (release/acquire)
        asm volatile("barrier.cluster.arrive.aligned;" ::: "memory");
        asm volatile("barrier.cluster.wait.aligned;" ::: "memory");

        // ---- fold flags & counts (64 uint16) ----
        uint32_t fand = 0xffffffffu, forr = 0u;
        unsigned int csum = 0u;
        const uint4* fc4 = reinterpret_cast<const uint4*>(&s_fc[wp][0]);
#pragma unroll
        for (int q8 = 0; q8 < 8; q8++) {
            uint4 vfc = fc4[q8];
            fand &= (vfc.x | 0xff00ff00u) & (vfc.y | 0xff00ff00u)
                  & (vfc.z | 0xff00ff00u) & (vfc.w | 0xff00ff00u);
            forr |= (vfc.x & 0x00ff00ffu) | (vfc.y & 0x00ff00ffu)
                  | (vfc.z & 0x00ff00ffu) | (vfc.w & 0x00ff00ffu);
            csum = __dp4a((vfc.x >> 8) & 0x00ff00ffu, 0x01010101u, csum);
            csum = __dp4a((vfc.y >> 8) & 0x00ff00ffu, 0x01010101u, csum);
            csum = __dp4a((vfc.z >> 8) & 0x00ff00ffu, 0x01010101u, csum);
            csum = __dp4a((vfc.w >> 8) & 0x00ff00ffu, 0x01010101u, csum);
        }
        fand &= fand >> 16;  forr |= forr >> 16;
        int ne_all = fand & 1;        int ne_any = (forr >> 1) & 1;
        int ni_all = (fand >> 2) & 1; int ni_any = (forr >> 3) & 1;
        int ecnt = (int)csum;

        if ((fand >> 4) & 1) { ts = st + 1; break; }   // absorbing saturation (uniform)

        // ---- list build: warp 0 = ez (spikers or complement, ascending e); warp 1 = iz ----
        if (warp == 0) {
            if (ne_any && !ne_all) {
                uint32_t w0 = s_ez[wp][2 * lane], w1 = s_ez[wp][2 * lane + 1];
                if (ecnt > 1024) { w0 = ~w0; w1 = ~w1; }
                int cnt = __popc(w0) + __popc(w1);
                int off = cnt;
#pragma unroll
                for (int d = 1; d < 32; d <<= 1) {
                    int nn = __shfl_up_sync(0xffffffffu, off, d);
                    if (lane >= d) off += nn;
                }
                off -= cnt;
                int be = lane * 64;
                while (w0) { int r = __ffs(w0) - 1; w0 &= w0 - 1;
                             s_elist[wp][off++] = (uint16_t)(be + r); }
                be += 32;
                while (w1) { int r = __ffs(w1) - 1; w1 &= w1 - 1;
                             s_elist[wp][off++] = (uint16_t)(be + r); }
            }
        } else if (warp == 1) {
            if (ni_any && !ni_all) {
                uint32_t m0 = (lane < IWORDS) ? s_iz[wp][lane] : 0u;
                int cnt = __popc(m0), off = cnt;
#pragma unroll
                for (int d = 1; d < 32; d <<= 1) {
                    int nn = __shfl_up_sync(0xffffffffu, off, d);
                    if (lane >= d) off += nn;
                }
                off -= cnt;
                int bi = lane * 32;
                while (m0) { int r = __ffs(m0) - 1; m0 &= m0 - 1;
                             s_ilist[wp][off++] = (uint16_t)(bi + r); }
            }
        }
        __syncthreads();   // lists visible

        // ---- [d] inhibitory current update via ez list (count-proportional, coalesced) ----
        if (t < 64) {
            float xi;
            if (ne_all)       xi = cwei;
            else if (!ne_any) xi = 0.f;
            else {
                int n = (ecnt <= 1024) ? ecnt : (EN - ecnt);
                float s = 0.f;
#pragma unroll 4
                for (int k = 0; k < n; k++) {
                    int e = s_elist[wp][k];
                    s = __fadd_rn(s, wei[(size_t)e * IN_ + i0]);
                }
                xi = (ecnt <= 1024) ? s : __fsub_rn(cwei, s);
            }
            ii = __fadd_rn(ii_dec, xi);
        }
        pe_all = ne_all; pe_any = ne_any; pi_all = ni_all; pi_any = ni_any;
    }

    // ---- fused fill: rows [ts, TN), this CTA writes its 512-float quarter ----
    const float4 ones = make_float4(1.f, 1.f, 1.f, 1.f);
    for (int r = ts; r < TN; r++) {
        if (t < 128) {
            float4* o4 = reinterpret_cast<float4*>(out + ((size_t)r * BN + b) * EN)
                       + (int)rank * 128 + t;
            __stcs(o4, ones);
        }
    }
}

extern "C" void kernel_launch(void* const* d_in, const int* in_sizes, int n_in,
                              void* d_out, int out_size)
{
    const float* x     = (const float*)d_in[0];  // [T,B,E]
    // d_in[1] = w_in (identity) -- exact pass-through, unused
    const float* w_rec = (const float*)d_in[2];  // [E,E]
    const float* w_ei  = (const float*)d_in[3];  // [E,I]
    const float* w_ie  = (const float*)d_in[4];  // [I,E]
    float* out = (float*)d_out;

    const int dsmem = 16 * 512 * sizeof(uint4);  // 128KB wrec quarter
    cudaFuncSetAttribute(sim_kernel, cudaFuncAttributeMaxDynamicSharedMemorySize, dsmem);

    prep1<<<128, 256>>>(w_rec);
    prep2<<<9 + 256, 256>>>(x, w_ie, w_ei);
    sim_kernel<<<BN * CLN, NT, dsmem>>>(x, w_ei, w_ie, out);
}